// round 16
// baseline (speedup 1.0000x reference)
#include <cuda_runtime.h>
#include <cuda_fp16.h>
#include <stdint.h>
#include <math.h>

#define BB 2
#define HH 16
#define SS 2048
#define DD 1024
#define DH 64
#define MROWS (BB*SS)          // 4096
#define KU 512                 // u32 (fp16x2) per DD row
#define TU 1024                // u32 (fp16x2) per SS row

static const size_t OUT_ELEMS  = (size_t)BB * SS * DD;        // 4,194,304
static const size_t ATTN_ELEMS = (size_t)BB * HH * SS * SS;   // 134,217,728

// Scratch (__device__ globals)
__device__ uint32_t g_qh[MROWS * KU];
__device__ uint32_t g_kh[MROWS * KU];
__device__ uint32_t g_vh[MROWS * KU];
__device__ uint32_t g_wqp[(DD/2) * DD];
__device__ uint32_t g_wkp[(DD/2) * DD];
__device__ uint32_t g_wvp[(DD/2) * DD];
__device__ uint32_t g_wop[(DD/2) * DD];
__device__ uint32_t g_qp[MROWS * KU];          // pre-scaled by 0.125
__device__ uint32_t g_kp[MROWS * KU];
__device__ uint32_t g_vp[MROWS * KU];
__device__ uint32_t g_vpt[(size_t)BB*HH*DH*TU];
__device__ uint32_t g_ctx[MROWS * KU];
__device__ uint32_t g_e_fb[(size_t)BB*HH*SS*TU];   // fallback e staging

// ---------------------------------------------------------------------------
__device__ __forceinline__ uint32_t packh2(float a, float b) {
    __half2 h = __floats2half2_rn(a, b);
    return *reinterpret_cast<uint32_t*>(&h);
}
__device__ __forceinline__ float2 unpackh2(uint32_t u) {
    __half2 h = *reinterpret_cast<__half2*>(&u);
    return __half22float2(h);
}
__device__ __forceinline__ float ex2f(float x) {
    float y;
    asm("ex2.approx.ftz.f32 %0, %1;" : "=f"(y) : "f"(x));
    return y;
}

__device__ __forceinline__ void mma_f16(float c[4], const uint32_t a[4],
                                        const uint32_t b[2]) {
    asm volatile(
        "mma.sync.aligned.m16n8k16.row.col.f32.f16.f16.f32 "
        "{%0,%1,%2,%3}, {%4,%5,%6,%7}, {%8,%9}, {%0,%1,%2,%3};\n"
        : "+f"(c[0]), "+f"(c[1]), "+f"(c[2]), "+f"(c[3])
        : "r"(a[0]), "r"(a[1]), "r"(a[2]), "r"(a[3]), "r"(b[0]), "r"(b[1]));
}

__device__ __forceinline__ uint32_t smaddr(const void* p) {
    return (uint32_t)__cvta_generic_to_shared(p);
}
__device__ __forceinline__ void ldsm4(uint32_t r[4], const uint32_t* p) {
    uint32_t a = smaddr(p);
    asm volatile(
        "ldmatrix.sync.aligned.m8n8.x4.shared.b16 {%0,%1,%2,%3}, [%4];"
        : "=r"(r[0]), "=r"(r[1]), "=r"(r[2]), "=r"(r[3]) : "r"(a));
}

#define CP_ASYNC16(dst, src) \
    asm volatile("cp.async.cg.shared.global [%0], [%1], 16;" :: "r"(dst), "l"(src))
#define CP_COMMIT() asm volatile("cp.async.commit_group;")
#define CP_WAIT(n)  asm volatile("cp.async.wait_group %0;" :: "n"(n))

// ---------------------------------------------------------------------------
// conv: q,k,v -> fp16; weights -> fp16 packed along k.
// ---------------------------------------------------------------------------
__global__ __launch_bounds__(256) void conv_all(
    const float4* __restrict__ q, const float4* __restrict__ k,
    const float4* __restrict__ v,
    const float* __restrict__ wq, const float* __restrict__ wk,
    const float* __restrict__ wv, const float* __restrict__ wo,
    uint32_t* __restrict__ qh, uint32_t* __restrict__ kh,
    uint32_t* __restrict__ vh,
    uint32_t* __restrict__ wqp, uint32_t* __restrict__ wkp,
    uint32_t* __restrict__ wvp, uint32_t* __restrict__ wop)
{
    const int NQ4 = MROWS * DD / 4;       // 2^20
    const int NW4 = (DD/2) * DD / 4;      // 2^17
    const int TOT = 3 * NQ4 + 4 * NW4;
    for (int i = blockIdx.x * 256 + threadIdx.x; i < TOT; i += gridDim.x * 256) {
        if (i < 3 * NQ4) {
            int s = i >> 20;
            int off = i & (NQ4 - 1);
            const float4* src = (s == 0) ? q : (s == 1) ? k : v;
            uint32_t* dst = (s == 0) ? qh : (s == 1) ? kh : vh;
            float4 x = src[off];
            uint2 u = {packh2(x.x, x.y), packh2(x.z, x.w)};
            *(uint2*)(dst + (size_t)off * 2) = u;
        } else {
            int j = i - 3 * NQ4;
            int s = j >> 17;
            int off = j & (NW4 - 1);
            const float* W = (s == 0) ? wq : (s == 1) ? wk : (s == 2) ? wv : wo;
            uint32_t* dst = (s == 0) ? wqp : (s == 1) ? wkp : (s == 2) ? wvp : wop;
            int kp_ = off >> 8;
            int n4 = (off & 255) * 4;
            float4 a = *(const float4*)(W + (size_t)(2 * kp_) * DD + n4);
            float4 b = *(const float4*)(W + (size_t)(2 * kp_ + 1) * DD + n4);
            uint4 o = {packh2(a.x, b.x), packh2(a.y, b.y),
                       packh2(a.z, b.z), packh2(a.w, b.w)};
            *(uint4*)(dst + (size_t)kp_ * DD + n4) = o;
        }
    }
}

// ---------------------------------------------------------------------------
// fp16 GEMM: C = (A @ W + bias) * alpha. Block 128x128, BK=64.
// 3-stage cp.async, one sync per iteration. Dyn smem 107520 B.
// ---------------------------------------------------------------------------
template <bool F16OUT>
__device__ __forceinline__ void gemm16_core(
    const uint32_t* __restrict__ A, const uint32_t* __restrict__ Wp,
    const float* __restrict__ bias, void* __restrict__ Cout, float alpha)
{
    extern __shared__ uint32_t dyn[];
    const int AST = 128 * 36;
    const int WST = 32 * 136;
    const int STG = AST + WST;
    const int NIT = KU / 32;   // 16

    const int tid = threadIdx.x;
    const int lane = tid & 31;
    const int warp = tid >> 5;
    const int g = lane >> 2, t4 = lane & 3;
    const int warpM = warp >> 2, warpN = warp & 3;
    const int rowBase = blockIdx.y * 128;
    const int colBase = blockIdx.x * 128;
    const int mOff = warpM * 64, nOff = warpN * 32;

    auto prefetch = [&](int it, int s) {
        int k0u = it * 32;
        uint32_t* As = dyn + s * STG;
        uint32_t* Ws = dyn + s * STG + AST;
#pragma unroll
        for (int i = 0; i < 4; i++) {
            int l = tid + i * 256;
            int r = l >> 3, c = (l & 7) * 4;
            CP_ASYNC16(smaddr(&As[r * 36 + c]),
                       A + (size_t)(rowBase + r) * KU + k0u + c);
        }
#pragma unroll
        for (int i = 0; i < 4; i++) {
            int l = tid + i * 256;
            int r = l >> 5, nc = (l & 31) * 4;
            CP_ASYNC16(smaddr(&Ws[r * 136 + nc]),
                       Wp + (size_t)(k0u + r) * DD + colBase + nc);
        }
    };

    float acc[4][4][4];
#pragma unroll
    for (int m = 0; m < 4; m++)
#pragma unroll
        for (int n = 0; n < 4; n++)
#pragma unroll
            for (int i = 0; i < 4; i++) acc[m][n][i] = 0.f;

    prefetch(0, 0); CP_COMMIT();
    prefetch(1, 1); CP_COMMIT();

    for (int it = 0; it < NIT; it++) {
        if (it + 1 < NIT) { CP_WAIT(1); } else { CP_WAIT(0); }
        __syncthreads();
        if (it + 2 < NIT) { prefetch(it + 2, (it + 2) % 3); CP_COMMIT(); }

        const uint32_t* As = dyn + (it % 3) * STG;
        const uint32_t* Ws = As + AST;
#pragma unroll
        for (int ks = 0; ks < 4; ks++) {
            int kb = ks * 8;
            uint32_t af[4][4], bf[4][2];
#pragma unroll
            for (int m = 0; m < 4; m++) {
                int mr = mOff + m * 16 + g;
                af[m][0] = As[mr * 36 + kb + t4];
                af[m][1] = As[(mr + 8) * 36 + kb + t4];
                af[m][2] = As[mr * 36 + kb + t4 + 4];
                af[m][3] = As[(mr + 8) * 36 + kb + t4 + 4];
            }
#pragma unroll
            for (int n = 0; n < 4; n++) {
                int nc = nOff + n * 8 + g;
                bf[n][0] = Ws[(kb + t4) * 136 + nc];
                bf[n][1] = Ws[(kb + t4 + 4) * 136 + nc];
            }
#pragma unroll
            for (int m = 0; m < 4; m++)
#pragma unroll
                for (int n = 0; n < 4; n++) mma_f16(acc[m][n], af[m], bf[n]);
        }
    }

#pragma unroll
    for (int m = 0; m < 4; m++) {
        int r0 = rowBase + mOff + m * 16 + g;
#pragma unroll
        for (int n = 0; n < 4; n++) {
            int c0 = colBase + nOff + n * 8 + t4 * 2;
            float2 bv = *(const float2*)(bias + c0);
            float v00 = (acc[m][n][0] + bv.x) * alpha;
            float v01 = (acc[m][n][1] + bv.y) * alpha;
            float v10 = (acc[m][n][2] + bv.x) * alpha;
            float v11 = (acc[m][n][3] + bv.y) * alpha;
            if (F16OUT) {
                uint32_t* C = (uint32_t*)Cout;
                C[(size_t)r0 * KU + (c0 >> 1)] = packh2(v00, v01);
                C[(size_t)(r0 + 8) * KU + (c0 >> 1)] = packh2(v10, v11);
            } else {
                float* C = (float*)Cout;
                float2 o0 = {v00, v01}, o1 = {v10, v11};
                *(float2*)(C + (size_t)r0 * DD + c0) = o0;
                *(float2*)(C + (size_t)(r0 + 8) * DD + c0) = o1;
            }
        }
    }
}

__global__ __launch_bounds__(256, 2) void proj_qkv_tc(
    const uint32_t* __restrict__ qh, const uint32_t* __restrict__ kh,
    const uint32_t* __restrict__ vh,
    const uint32_t* __restrict__ wqp, const uint32_t* __restrict__ wkp,
    const uint32_t* __restrict__ wvp,
    const float* __restrict__ bq, const float* __restrict__ bk,
    const float* __restrict__ bv,
    uint32_t* __restrict__ qp, uint32_t* __restrict__ kp,
    uint32_t* __restrict__ vp)
{
    int z = blockIdx.z;
    const uint32_t* A = (z == 0) ? qh : (z == 1) ? kh : vh;
    const uint32_t* W = (z == 0) ? wqp : (z == 1) ? wkp : wvp;
    const float* B    = (z == 0) ? bq : (z == 1) ? bk : bv;
    uint32_t* C       = (z == 0) ? qp : (z == 1) ? kp : vp;
    float alpha       = (z == 0) ? 0.125f : 1.0f;
    gemm16_core<true>(A, W, B, C, alpha);
}

__global__ __launch_bounds__(256, 2) void out_proj_tc(
    const uint32_t* __restrict__ A, const uint32_t* __restrict__ W,
    const float* __restrict__ B, float* __restrict__ C)
{
    gemm16_core<false>(A, W, B, C, 1.0f);
}

// ---------------------------------------------------------------------------
// V head-transpose: vp fp16 [b][t][h*64+d] -> vpt [bh][d][t]
// ---------------------------------------------------------------------------
__global__ __launch_bounds__(256) void transpose_v(
    const uint32_t* __restrict__ vp, uint32_t* __restrict__ vpt)
{
    __shared__ uint16_t Ts[64][66];
    const int tid = threadIdx.x;
    const int bh = blockIdx.y, b = bh >> 4, h = bh & 15;
    const int t0 = blockIdx.x * 64;

#pragma unroll
    for (int i = 0; i < 8; i++) {
        int l = tid + i * 256;
        int r = l >> 5, c = l & 31;
        uint32_t x = vp[(size_t)(b * SS + t0 + r) * KU + h * (DH/2) + c];
        *(uint32_t*)&Ts[r][2 * c] = x;
    }
    __syncthreads();
#pragma unroll
    for (int i = 0; i < 8; i++) {
        int l = tid + i * 256;
        int d = l >> 5, tc = l & 31;
        uint32_t lo = Ts[2 * tc][d];
        uint32_t hi = Ts[2 * tc + 1][d];
        vpt[(size_t)bh * DH * TU + (size_t)d * TU + (t0 >> 1) + tc] =
            lo | (hi << 16);
    }
}

// ---------------------------------------------------------------------------
// Fused attention with in-place e-staging.
// Pass 1: QK + exp, e fp16 pairs -> eb (upper half of attn_out rows, or
//         fallback buffer), row sums -> invL.
// Pass 2: cp.async e + V tiles; ldmatrix e as A-fragments; PV MMAs only;
//         p = e * invL written from the same fragments (WRITEP).
// 128 threads, 4 warps x 32 s-rows. 2-stage pipelines (round-14 structure).
// Dyn smem: msk fp16[2048] + ILs f32[128] + 2 x (E[128][36]+V[64][36]) u32.
// ---------------------------------------------------------------------------
template <bool WRITEP>
__global__ __launch_bounds__(128, 3) void attn_fused(
    const uint32_t* __restrict__ qp, const uint32_t* __restrict__ kp,
    const uint32_t* __restrict__ vpt, const float* __restrict__ mask,
    float* attn_out, uint32_t* eb, int ESTR, uint32_t* __restrict__ ctx)
{
    extern __shared__ uint32_t dynf[];
    uint32_t* mskU = dynf;                 // [1024] u32 = 2048 fp16
    float* ILs = (float*)(dynf + 1024);    // [128]
    uint32_t* stg = dynf + 1024 + 128;
    const int KSZ1 = 64 * 36;              // pass-1 K stage
    const int ESZ = 128 * 36, VSZ = 64 * 36, STG2 = ESZ + VSZ;
    const int NIT = 32;

    const int tid = threadIdx.x;
    const int lane = tid & 31;
    const int warp = tid >> 5;             // 0..3
    const int g = lane >> 2, t4 = lane & 3;
    const int bh = blockIdx.y, b = bh >> 4, h = bh & 15;
    const int s0 = blockIdx.x * 128;
    const float L2E = 1.44269504089f;

    // ldmatrix lane maps
    const int lrowB = ((lane >> 4) & 1) * 8 + (lane & 7);   // B operands
    const int lcolB = ((lane >> 3) & 1) * 4;
    const int lrowA = ((lane >> 3) & 1) * 8 + (lane & 7);   // A operands
    const int lcolA = ((lane >> 4) & 1) * 4;

    const uint32_t* qb = qp + (size_t)b * SS * KU + h * 32;
    const uint32_t* kb = kp + (size_t)b * SS * KU + h * 32;
    const uint32_t* vb = vpt + (size_t)bh * DH * TU;
    uint32_t* ebb = eb + (size_t)(bh * SS + s0) * ESTR;   // block's e rows

    // mask -> smem as clamped fp16 pairs (pre-scaled by -1e9*log2e)
    for (int i = tid; i < 1024; i += 128) {
        float2 mv = *(const float2*)(mask + (size_t)b * SS + 2 * i);
        float a = fmaxf(mv.x * (-1e9f * L2E), -60000.f);
        float c = fmaxf(mv.y * (-1e9f * L2E), -60000.f);
        mskU[i] = packh2(a, c);
    }

    // Q -> stage area -> registers (held through pass 1)
    {
        uint32_t* Qs = stg;
#pragma unroll
        for (int i = 0; i < 8; i++) {
            int l = tid + i * 128;
            int r = l >> 3, c = (l & 7) * 4;
            CP_ASYNC16(smaddr(&Qs[r * 36 + c]), qb + (size_t)(s0 + r) * KU + c);
        }
        CP_COMMIT(); CP_WAIT(0);
        __syncthreads();
    }
    uint32_t qf[2][4][4];
    {
        const uint32_t* Qs = stg;
#pragma unroll
        for (int m = 0; m < 2; m++) {
            int mr = warp * 32 + m * 16 + g;
#pragma unroll
            for (int kt = 0; kt < 4; kt++) {
                qf[m][kt][0] = Qs[mr * 36 + kt * 8 + t4];
                qf[m][kt][1] = Qs[(mr + 8) * 36 + kt * 8 + t4];
                qf[m][kt][2] = Qs[mr * 36 + kt * 8 + t4 + 4];
                qf[m][kt][3] = Qs[(mr + 8) * 36 + kt * 8 + t4 + 4];
            }
        }
    }
    __syncthreads();

    auto prefK = [&](int it, int st) {
        uint32_t* Ks = stg + st * KSZ1;
#pragma unroll
        for (int i = 0; i < 4; i++) {
            int l = tid + i * 128;
            int r = l >> 3, c = (l & 7) * 4;
            CP_ASYNC16(smaddr(&Ks[r * 36 + c]),
                       kb + (size_t)(it * 64 + r) * KU + c);
        }
    };

    // ---------------- Pass 1: QK + exp + e-store + row sums ----------------
    float rs[2][2] = {{0.f, 0.f}, {0.f, 0.f}};
    prefK(0, 0); CP_COMMIT();
    for (int it = 0; it < NIT; it++) {
        if (it + 1 < NIT) { prefK(it + 1, (it + 1) & 1); CP_COMMIT(); CP_WAIT(1); }
        else { CP_WAIT(0); }
        __syncthreads();
        const uint32_t* Ks = stg + (it & 1) * KSZ1;
#pragma unroll
        for (int ntp = 0; ntp < 4; ntp++) {
            uint32_t kr[4][4];
#pragma unroll
            for (int kt = 0; kt < 4; kt++)
                ldsm4(kr[kt], Ks + (ntp * 16 + lrowB) * 36 + kt * 8 + lcolB);
            uint32_t mua = mskU[it * 32 + ntp * 8 + t4];
            uint32_t mub = mskU[it * 32 + ntp * 8 + 4 + t4];
            float2 mka = __half22float2(*(__half2*)&mua);
            float2 mkb = __half22float2(*(__half2*)&mub);
#pragma unroll
            for (int m = 0; m < 2; m++) {
                float ca[4] = {0.f, 0.f, 0.f, 0.f};
                float cb[4] = {0.f, 0.f, 0.f, 0.f};
#pragma unroll
                for (int kt = 0; kt < 4; kt++) {
                    mma_f16(ca, qf[m][kt], &kr[kt][0]);
                    mma_f16(cb, qf[m][kt], &kr[kt][2]);
                }
                float e0a = ex2f(fmaf(ca[0], L2E, mka.x));
                float e1a = ex2f(fmaf(ca[1], L2E, mka.y));
                float e2a = ex2f(fmaf(ca[2], L2E, mka.x));
                float e3a = ex2f(fmaf(ca[3], L2E, mka.y));
                float e0b = ex2f(fmaf(cb[0], L2E, mkb.x));
                float e1b = ex2f(fmaf(cb[1], L2E, mkb.y));
                float e2b = ex2f(fmaf(cb[2], L2E, mkb.x));
                float e3b = ex2f(fmaf(cb[3], L2E, mkb.y));
                rs[m][0] += e0a + e1a + e0b + e1b;
                rs[m][1] += e2a + e3a + e2b + e3b;

                // store e fp16 pairs
                uint32_t* er = ebb + (size_t)(warp * 32 + m * 16 + g) * ESTR
                               + it * 32 + ntp * 8;
                er[t4] = packh2(e0a, e1a);
                er[4 + t4] = packh2(e0b, e1b);
                uint32_t* er8 = er + (size_t)8 * ESTR;
                er8[t4] = packh2(e2a, e3a);
                er8[4 + t4] = packh2(e2b, e3b);
            }
        }
        __syncthreads();
    }
#pragma unroll
    for (int m = 0; m < 2; m++)
#pragma unroll
        for (int hh = 0; hh < 2; hh++) {
            float s = rs[m][hh];
            s += __shfl_xor_sync(0xffffffffu, s, 1);
            s += __shfl_xor_sync(0xffffffffu, s, 2);
            if (t4 == 0) ILs[warp * 32 + m * 16 + g + hh * 8] = 1.0f / s;
        }
    __syncthreads();
    float il[2][2];
#pragma unroll
    for (int m = 0; m < 2; m++) {
        il[m][0] = ILs[warp * 32 + m * 16 + g];
        il[m][1] = ILs[warp * 32 + m * 16 + g + 8];
    }

    // ---------------- Pass 2: e + V -> PV, p-write --------------------------
    auto prefE = [&](int it, int st) {
        uint32_t* Es = stg + st * STG2;
#pragma unroll
        for (int i = 0; i < 8; i++) {
            int l = tid + i * 128;
            int r = l >> 3, c = (l & 7) * 4;
            CP_ASYNC16(smaddr(&Es[r * 36 + c]),
                       ebb + (size_t)r * ESTR + it * 32 + c);
        }
    };
    auto prefV = [&](int it, int st) {
        uint32_t* Vs = stg + st * STG2 + ESZ;
#pragma unroll
        for (int i = 0; i < 4; i++) {
            int l = tid + i * 128;
            int d = l >> 3, c = (l & 7) * 4;
            CP_ASYNC16(smaddr(&Vs[d * 36 + c]),
                       vb + (size_t)d * TU + it * 32 + c);
        }
    };

    float accv[2][8][4];
#pragma unroll
    for (int m = 0; m < 2; m++)
#pragma unroll
        for (int dt = 0; dt < 8; dt++)
#pragma unroll
            for (int i = 0; i < 4; i++) accv[m][dt][i] = 0.f;

    prefE(0, 0); prefV(0, 0); CP_COMMIT();
    for (int it = 0; it < NIT; it++) {
        if (it + 1 < NIT) {
            prefE(it + 1, (it + 1) & 1); prefV(it + 1, (it + 1) & 1);
            CP_COMMIT(); CP_WAIT(1);
        } else { CP_WAIT(0); }
        __syncthreads();
        const uint32_t* Es = stg + (it & 1) * STG2;
        const uint32_t* Vs = Es + ESZ;
#pragma unroll
        for (int ntp = 0; ntp < 4; ntp++) {
            uint32_t ef[2][4];
#pragma unroll
            for (int m = 0; m < 2; m++)
                ldsm4(ef[m], Es + (warp * 32 + m * 16 + lrowA) * 36
                             + ntp * 8 + lcolA);

            if (WRITEP) {
#pragma unroll
                for (int m = 0; m < 2; m++) {
                    int row = s0 + warp * 32 + m * 16 + g;
                    int col = it * 64 + ntp * 16 + t4 * 2;
                    float2 fa = unpackh2(ef[m][0]);
                    float2 fb = unpackh2(ef[m][1]);
                    float2 fc = unpackh2(ef[m][2]);
                    float2 fd = unpackh2(ef[m][3]);
                    float* o0 = attn_out + ((size_t)bh * SS + row) * SS + col;
                    float* o1 = attn_out + ((size_t)bh * SS + row + 8) * SS + col;
                    float2 p0a = {fa.x * il[m][0], fa.y * il[m][0]};
                    float2 p1a = {fb.x * il[m][1], fb.y * il[m][1]};
                    float2 p0b = {fc.x * il[m][0], fc.y * il[m][0]};
                    float2 p1b = {fd.x * il[m][1], fd.y * il[m][1]};
                    *(float2*)o0 = p0a;
                    *(float2*)(o0 + 8) = p0b;
                    *(float2*)o1 = p1a;
                    *(float2*)(o1 + 8) = p1b;
                }
            }

            const int ku = ntp * 8;
#pragma unroll
            for (int dp = 0; dp < 4; dp++) {
                uint32_t vr[4];
                ldsm4(vr, Vs + (dp * 16 + lrowB) * 36 + ku + lcolB);
#pragma unroll
                for (int m = 0; m < 2; m++) {
                    mma_f16(accv[m][2 * dp], ef[m], &vr[0]);
                    mma_f16(accv[m][2 * dp + 1], ef[m], &vr[2]);
                }
            }
        }
        __syncthreads();
    }

    // ctx epilogue: scale by invL, store fp16
#pragma unroll
    for (int m = 0; m < 2; m++) {
        int mr = warp * 32 + m * 16 + g;
#pragma unroll
        for (int dt = 0; dt < 8; dt++) {
            uint32_t o0 = packh2(accv[m][dt][0] * il[m][0],
                                 accv[m][dt][1] * il[m][0]);
            uint32_t o1 = packh2(accv[m][dt][2] * il[m][1],
                                 accv[m][dt][3] * il[m][1]);
            ctx[((size_t)b * SS + s0 + mr) * KU + h * 32 + dt * 4 + t4] = o0;
            ctx[((size_t)b * SS + s0 + mr + 8) * KU + h * 32 + dt * 4 + t4] = o1;
        }
    }
}

// ---------------------------------------------------------------------------
extern "C" void kernel_launch(void* const* d_in, const int* in_sizes, int n_in,
                              void* d_out, int out_size)
{
    const float* q    = (const float*)d_in[0];
    const float* k    = (const float*)d_in[1];
    const float* v    = (const float*)d_in[2];
    const float* mask = (const float*)d_in[3];
    const float* wq   = (const float*)d_in[4];
    const float* bq   = (const float*)d_in[5];
    const float* wk   = (const float*)d_in[6];
    const float* bk   = (const float*)d_in[7];
    const float* wv   = (const float*)d_in[8];
    const float* bv   = (const float*)d_in[9];
    const float* wo   = (const float*)d_in[10];
    const float* bo   = (const float*)d_in[11];
    float* out = (float*)d_out;

    uint32_t *qh, *kh, *vh, *wqp, *wkp, *wvp, *wop, *qp, *kp, *vp, *vpt, *ctx, *efb;
    cudaGetSymbolAddress((void**)&qh,  g_qh);
    cudaGetSymbolAddress((void**)&kh,  g_kh);
    cudaGetSymbolAddress((void**)&vh,  g_vh);
    cudaGetSymbolAddress((void**)&wqp, g_wqp);
    cudaGetSymbolAddress((void**)&wkp, g_wkp);
    cudaGetSymbolAddress((void**)&wvp, g_wvp);
    cudaGetSymbolAddress((void**)&wop, g_wop);
    cudaGetSymbolAddress((void**)&qp,  g_qp);
    cudaGetSymbolAddress((void**)&kp,  g_kp);
    cudaGetSymbolAddress((void**)&vp,  g_vp);
    cudaGetSymbolAddress((void**)&vpt, g_vpt);
    cudaGetSymbolAddress((void**)&ctx, g_ctx);
    cudaGetSymbolAddress((void**)&efb, g_e_fb);

    bool attn_in_out = ((size_t)out_size >= OUT_ELEMS + ATTN_ELEMS);
    float* attn_out = attn_in_out ? (out + OUT_ELEMS) : nullptr;

    const int DYN_G = 3 * (128 * 36 + 32 * 136) * 4;            // 107520
    const int DYN_A = (1024 + 128 + 2 * (128 * 36 + 64 * 36)) * 4; // 59904
    cudaFuncSetAttribute(proj_qkv_tc, cudaFuncAttributeMaxDynamicSharedMemorySize, DYN_G);
    cudaFuncSetAttribute(out_proj_tc, cudaFuncAttributeMaxDynamicSharedMemorySize, DYN_G);
    cudaFuncSetAttribute(attn_fused<true>,  cudaFuncAttributeMaxDynamicSharedMemorySize, DYN_A);
    cudaFuncSetAttribute(attn_fused<false>, cudaFuncAttributeMaxDynamicSharedMemorySize, DYN_A);

    conv_all<<<2048, 256>>>(
        (const float4*)q, (const float4*)k, (const float4*)v,
        wq, wk, wv, wo,
        qh, kh, vh, wqp, wkp, wvp, wop);

    proj_qkv_tc<<<dim3(DD / 128, MROWS / 128, 3), 256, DYN_G>>>(
        qh, kh, vh, wqp, wkp, wvp, bq, bk, bv, qp, kp, vp);

    transpose_v<<<dim3(SS / 64, BB * HH), 256>>>(vp, vpt);

    if (attn_in_out) {
        // e staged in the upper half of each attn_out row (u32 slots 1024+)
        uint32_t* eb = (uint32_t*)attn_out + 1024;
        attn_fused<true><<<dim3(SS / 128, BB * HH), 128, DYN_A>>>(
            qp, kp, vpt, mask, attn_out, eb, 2048, ctx);
    } else {
        attn_fused<false><<<dim3(SS / 128, BB * HH), 128, DYN_A>>>(
            qp, kp, vpt, mask, nullptr, efb, 1024, ctx);
    }

    out_proj_tc<<<dim3(DD / 128, MROWS / 128), 256, DYN_G>>>(ctx, wop, bo, out);
}

// round 17
// speedup vs baseline: 1.7019x; 1.7019x over previous
#include <cuda_runtime.h>
#include <cuda_fp16.h>
#include <stdint.h>
#include <math.h>

#define BB 2
#define HH 16
#define SS 2048
#define DD 1024
#define DH 64
#define MROWS (BB*SS)          // 4096
#define KU 512                 // u32 (fp16x2) per DD row
#define TU 1024                // u32 (fp16x2) per SS row

static const size_t OUT_ELEMS  = (size_t)BB * SS * DD;        // 4,194,304
static const size_t ATTN_ELEMS = (size_t)BB * HH * SS * SS;   // 134,217,728

// Scratch (__device__ globals)
__device__ uint32_t g_qh[MROWS * KU];
__device__ uint32_t g_kh[MROWS * KU];
__device__ uint32_t g_vh[MROWS * KU];
__device__ uint32_t g_wqp[(DD/2) * DD];
__device__ uint32_t g_wkp[(DD/2) * DD];
__device__ uint32_t g_wvp[(DD/2) * DD];
__device__ uint32_t g_wop[(DD/2) * DD];
__device__ uint32_t g_qp[MROWS * KU];          // pre-scaled by 0.125
__device__ uint32_t g_kp[MROWS * KU];
__device__ uint32_t g_vp[MROWS * KU];
__device__ uint32_t g_vpt[(size_t)BB*HH*DH*TU];
__device__ uint32_t g_ctx[MROWS * KU];

// ---------------------------------------------------------------------------
__device__ __forceinline__ uint32_t packh2(float a, float b) {
    __half2 h = __floats2half2_rn(a, b);
    return *reinterpret_cast<uint32_t*>(&h);
}
__device__ __forceinline__ float2 unpackh2(uint32_t u) {
    __half2 h = *reinterpret_cast<__half2*>(&u);
    return __half22float2(h);
}
__device__ __forceinline__ float ex2f(float x) {
    float y;
    asm("ex2.approx.ftz.f32 %0, %1;" : "=f"(y) : "f"(x));
    return y;
}

__device__ __forceinline__ void mma_f16(float c[4], const uint32_t a[4],
                                        const uint32_t b[2]) {
    asm volatile(
        "mma.sync.aligned.m16n8k16.row.col.f32.f16.f16.f32 "
        "{%0,%1,%2,%3}, {%4,%5,%6,%7}, {%8,%9}, {%0,%1,%2,%3};\n"
        : "+f"(c[0]), "+f"(c[1]), "+f"(c[2]), "+f"(c[3])
        : "r"(a[0]), "r"(a[1]), "r"(a[2]), "r"(a[3]), "r"(b[0]), "r"(b[1]));
}

__device__ __forceinline__ uint32_t smaddr(const void* p) {
    return (uint32_t)__cvta_generic_to_shared(p);
}
__device__ __forceinline__ void ldsm4(uint32_t r[4], const uint32_t* p) {
    uint32_t a = smaddr(p);
    asm volatile(
        "ldmatrix.sync.aligned.m8n8.x4.shared.b16 {%0,%1,%2,%3}, [%4];"
        : "=r"(r[0]), "=r"(r[1]), "=r"(r[2]), "=r"(r[3]) : "r"(a));
}

#define CP_ASYNC16(dst, src) \
    asm volatile("cp.async.cg.shared.global [%0], [%1], 16;" :: "r"(dst), "l"(src))
#define CP_COMMIT() asm volatile("cp.async.commit_group;")
#define CP_WAIT(n)  asm volatile("cp.async.wait_group %0;" :: "n"(n))

// ---------------------------------------------------------------------------
// conv: q,k,v -> fp16; weights -> fp16 packed along k.
// ---------------------------------------------------------------------------
__global__ __launch_bounds__(256) void conv_all(
    const float4* __restrict__ q, const float4* __restrict__ k,
    const float4* __restrict__ v,
    const float* __restrict__ wq, const float* __restrict__ wk,
    const float* __restrict__ wv, const float* __restrict__ wo,
    uint32_t* __restrict__ qh, uint32_t* __restrict__ kh,
    uint32_t* __restrict__ vh,
    uint32_t* __restrict__ wqp, uint32_t* __restrict__ wkp,
    uint32_t* __restrict__ wvp, uint32_t* __restrict__ wop)
{
    const int NQ4 = MROWS * DD / 4;       // 2^20
    const int NW4 = (DD/2) * DD / 4;      // 2^17
    const int TOT = 3 * NQ4 + 4 * NW4;
    for (int i = blockIdx.x * 256 + threadIdx.x; i < TOT; i += gridDim.x * 256) {
        if (i < 3 * NQ4) {
            int s = i >> 20;
            int off = i & (NQ4 - 1);
            const float4* src = (s == 0) ? q : (s == 1) ? k : v;
            uint32_t* dst = (s == 0) ? qh : (s == 1) ? kh : vh;
            float4 x = src[off];
            uint2 u = {packh2(x.x, x.y), packh2(x.z, x.w)};
            *(uint2*)(dst + (size_t)off * 2) = u;
        } else {
            int j = i - 3 * NQ4;
            int s = j >> 17;
            int off = j & (NW4 - 1);
            const float* W = (s == 0) ? wq : (s == 1) ? wk : (s == 2) ? wv : wo;
            uint32_t* dst = (s == 0) ? wqp : (s == 1) ? wkp : (s == 2) ? wvp : wop;
            int kp_ = off >> 8;
            int n4 = (off & 255) * 4;
            float4 a = *(const float4*)(W + (size_t)(2 * kp_) * DD + n4);
            float4 b = *(const float4*)(W + (size_t)(2 * kp_ + 1) * DD + n4);
            uint4 o = {packh2(a.x, b.x), packh2(a.y, b.y),
                       packh2(a.z, b.z), packh2(a.w, b.w)};
            *(uint4*)(dst + (size_t)kp_ * DD + n4) = o;
        }
    }
}

// ---------------------------------------------------------------------------
// fp16 GEMM: C = (A @ W + bias) * alpha. Block 128x128, BK=64, 2-stage.
// ---------------------------------------------------------------------------
template <bool F16OUT>
__device__ __forceinline__ void gemm16_core(
    const uint32_t* __restrict__ A, const uint32_t* __restrict__ Wp,
    const float* __restrict__ bias, void* __restrict__ Cout, float alpha)
{
    extern __shared__ uint32_t dyn[];
    const int AST = 128 * 36;
    const int WST = 32 * 136;
    const int STG = AST + WST;

    const int tid = threadIdx.x;
    const int lane = tid & 31;
    const int warp = tid >> 5;
    const int g = lane >> 2, t4 = lane & 3;
    const int warpM = warp >> 2, warpN = warp & 3;
    const int rowBase = blockIdx.y * 128;
    const int colBase = blockIdx.x * 128;
    const int mOff = warpM * 64, nOff = warpN * 32;

    auto prefetch = [&](int k0u, int s) {
        uint32_t* As = dyn + s * STG;
        uint32_t* Ws = dyn + s * STG + AST;
#pragma unroll
        for (int i = 0; i < 4; i++) {
            int l = tid + i * 256;
            int r = l >> 3, c = (l & 7) * 4;
            CP_ASYNC16(smaddr(&As[r * 36 + c]),
                       A + (size_t)(rowBase + r) * KU + k0u + c);
        }
#pragma unroll
        for (int i = 0; i < 4; i++) {
            int l = tid + i * 256;
            int r = l >> 5, nc = (l & 31) * 4;
            CP_ASYNC16(smaddr(&Ws[r * 136 + nc]),
                       Wp + (size_t)(k0u + r) * DD + colBase + nc);
        }
    };

    float acc[4][4][4];
#pragma unroll
    for (int m = 0; m < 4; m++)
#pragma unroll
        for (int n = 0; n < 4; n++)
#pragma unroll
            for (int i = 0; i < 4; i++) acc[m][n][i] = 0.f;

    prefetch(0, 0);
    CP_COMMIT();

    int stage = 0;
    for (int k0u = 0; k0u < KU; k0u += 32) {
        if (k0u + 32 < KU) {
            prefetch(k0u + 32, stage ^ 1);
            CP_COMMIT();
            CP_WAIT(1);
        } else {
            CP_WAIT(0);
        }
        __syncthreads();

        const uint32_t* As = dyn + stage * STG;
        const uint32_t* Ws = dyn + stage * STG + AST;
#pragma unroll
        for (int ks = 0; ks < 4; ks++) {
            int kb = ks * 8;
            uint32_t af[4][4], bf[4][2];
#pragma unroll
            for (int m = 0; m < 4; m++) {
                int mr = mOff + m * 16 + g;
                af[m][0] = As[mr * 36 + kb + t4];
                af[m][1] = As[(mr + 8) * 36 + kb + t4];
                af[m][2] = As[mr * 36 + kb + t4 + 4];
                af[m][3] = As[(mr + 8) * 36 + kb + t4 + 4];
            }
#pragma unroll
            for (int n = 0; n < 4; n++) {
                int nc = nOff + n * 8 + g;
                bf[n][0] = Ws[(kb + t4) * 136 + nc];
                bf[n][1] = Ws[(kb + t4 + 4) * 136 + nc];
            }
#pragma unroll
            for (int m = 0; m < 4; m++)
#pragma unroll
                for (int n = 0; n < 4; n++) mma_f16(acc[m][n], af[m], bf[n]);
        }
        stage ^= 1;
        __syncthreads();
    }

#pragma unroll
    for (int m = 0; m < 4; m++) {
        int r0 = rowBase + mOff + m * 16 + g;
#pragma unroll
        for (int n = 0; n < 4; n++) {
            int c0 = colBase + nOff + n * 8 + t4 * 2;
            float2 bv = *(const float2*)(bias + c0);
            float v00 = (acc[m][n][0] + bv.x) * alpha;
            float v01 = (acc[m][n][1] + bv.y) * alpha;
            float v10 = (acc[m][n][2] + bv.x) * alpha;
            float v11 = (acc[m][n][3] + bv.y) * alpha;
            if (F16OUT) {
                uint32_t* C = (uint32_t*)Cout;
                C[(size_t)r0 * KU + (c0 >> 1)] = packh2(v00, v01);
                C[(size_t)(r0 + 8) * KU + (c0 >> 1)] = packh2(v10, v11);
            } else {
                float* C = (float*)Cout;
                float2 o0 = {v00, v01}, o1 = {v10, v11};
                *(float2*)(C + (size_t)r0 * DD + c0) = o0;
                *(float2*)(C + (size_t)(r0 + 8) * DD + c0) = o1;
            }
        }
    }
}

__global__ __launch_bounds__(256, 2) void proj_qkv_tc(
    const uint32_t* __restrict__ qh, const uint32_t* __restrict__ kh,
    const uint32_t* __restrict__ vh,
    const uint32_t* __restrict__ wqp, const uint32_t* __restrict__ wkp,
    const uint32_t* __restrict__ wvp,
    const float* __restrict__ bq, const float* __restrict__ bk,
    const float* __restrict__ bv,
    uint32_t* __restrict__ qp, uint32_t* __restrict__ kp,
    uint32_t* __restrict__ vp)
{
    int z = blockIdx.z;
    const uint32_t* A = (z == 0) ? qh : (z == 1) ? kh : vh;
    const uint32_t* W = (z == 0) ? wqp : (z == 1) ? wkp : wvp;
    const float* B    = (z == 0) ? bq : (z == 1) ? bk : bv;
    uint32_t* C       = (z == 0) ? qp : (z == 1) ? kp : vp;
    float alpha       = (z == 0) ? 0.125f : 1.0f;
    gemm16_core<true>(A, W, B, C, alpha);
}

__global__ __launch_bounds__(256, 2) void out_proj_tc(
    const uint32_t* __restrict__ A, const uint32_t* __restrict__ W,
    const float* __restrict__ B, float* __restrict__ C)
{
    gemm16_core<false>(A, W, B, C, 1.0f);
}

// ---------------------------------------------------------------------------
// V head-transpose: vp fp16 [b][t][h*64+d] -> vpt [bh][d][t]
// ---------------------------------------------------------------------------
__global__ __launch_bounds__(256) void transpose_v(
    const uint32_t* __restrict__ vp, uint32_t* __restrict__ vpt)
{
    __shared__ uint16_t Ts[64][66];
    const int tid = threadIdx.x;
    const int bh = blockIdx.y, b = bh >> 4, h = bh & 15;
    const int t0 = blockIdx.x * 64;

#pragma unroll
    for (int i = 0; i < 8; i++) {
        int l = tid + i * 256;
        int r = l >> 5, c = l & 31;
        uint32_t x = vp[(size_t)(b * SS + t0 + r) * KU + h * (DH/2) + c];
        *(uint32_t*)&Ts[r][2 * c] = x;
    }
    __syncthreads();
#pragma unroll
    for (int i = 0; i < 8; i++) {
        int l = tid + i * 256;
        int d = l >> 5, tc = l & 31;
        uint32_t lo = Ts[2 * tc][d];
        uint32_t hi = Ts[2 * tc + 1][d];
        vpt[(size_t)bh * DH * TU + (size_t)d * TU + (t0 >> 1) + tc] =
            lo | (hi << 16);
    }
}

// ---------------------------------------------------------------------------
// Fused attention (round-14 structure): 128 threads, 4 warps x 32 s-rows.
// Two passes over K in 64-row chunks, 2-stage cp.async.
// Pass-2 reorder: pack pf right after exp, run ALL PV MMAs, THEN write
// p = fp16(e)*il by unpacking pf (keeps tensor pipe fed; STGs at iter end).
// Dyn smem: msk fp16[2048] + ILs f32[128] + 2 x (K[64][36]+V[64][36]) u32
//         = 41472 B. __launch_bounds__(128,3).
// ---------------------------------------------------------------------------
template <bool WRITEP>
__global__ __launch_bounds__(128, 3) void attn_fused(
    const uint32_t* __restrict__ qp, const uint32_t* __restrict__ kp,
    const uint32_t* __restrict__ vpt, const float* __restrict__ mask,
    float* __restrict__ attn_out, uint32_t* __restrict__ ctx)
{
    extern __shared__ uint32_t dynf[];
    uint32_t* mskU = dynf;                 // [1024] u32 = 2048 fp16
    float* ILs = (float*)(dynf + 1024);    // [128]
    uint32_t* stg = dynf + 1024 + 128;
    const int KSZ = 64 * 36, STG = 2 * KSZ;   // K[64][36] + V[64][36]

    const int tid = threadIdx.x;
    const int lane = tid & 31;
    const int warp = tid >> 5;             // 0..3
    const int g = lane >> 2, t4 = lane & 3;
    const int bh = blockIdx.y, b = bh >> 4, h = bh & 15;
    const int s0 = blockIdx.x * 128;
    const float L2E = 1.44269504089f;

    const int lrowB = ((lane >> 4) & 1) * 8 + (lane & 7);
    const int lcolB = ((lane >> 3) & 1) * 4;

    const uint32_t* qb = qp + (size_t)b * SS * KU + h * 32;
    const uint32_t* kb = kp + (size_t)b * SS * KU + h * 32;
    const uint32_t* vb = vpt + (size_t)bh * DH * TU;

    // mask -> smem as clamped fp16 pairs (pre-scaled by -1e9*log2e)
    for (int i = tid; i < 1024; i += 128) {
        float2 mv = *(const float2*)(mask + (size_t)b * SS + 2 * i);
        float a = fmaxf(mv.x * (-1e9f * L2E), -60000.f);
        float c = fmaxf(mv.y * (-1e9f * L2E), -60000.f);
        mskU[i] = packh2(a, c);
    }

    // Q -> stage area -> registers (held for whole kernel)
    {
        uint32_t* Qs = stg;
#pragma unroll
        for (int i = 0; i < 8; i++) {
            int l = tid + i * 128;
            int r = l >> 3, c = (l & 7) * 4;
            CP_ASYNC16(smaddr(&Qs[r * 36 + c]), qb + (size_t)(s0 + r) * KU + c);
        }
        CP_COMMIT(); CP_WAIT(0);
        __syncthreads();
    }
    uint32_t qf[2][4][4];
    {
        const uint32_t* Qs = stg;
#pragma unroll
        for (int m = 0; m < 2; m++) {
            int mr = warp * 32 + m * 16 + g;
#pragma unroll
            for (int kt = 0; kt < 4; kt++) {
                qf[m][kt][0] = Qs[mr * 36 + kt * 8 + t4];
                qf[m][kt][1] = Qs[(mr + 8) * 36 + kt * 8 + t4];
                qf[m][kt][2] = Qs[mr * 36 + kt * 8 + t4 + 4];
                qf[m][kt][3] = Qs[(mr + 8) * 36 + kt * 8 + t4 + 4];
            }
        }
    }
    __syncthreads();

    auto prefK = [&](int it, int st) {
        uint32_t* Ks = stg + st * STG;
#pragma unroll
        for (int i = 0; i < 4; i++) {
            int l = tid + i * 128;
            int r = l >> 3, c = (l & 7) * 4;
            CP_ASYNC16(smaddr(&Ks[r * 36 + c]),
                       kb + (size_t)(it * 64 + r) * KU + c);
        }
    };
    auto prefV = [&](int it, int st) {
        uint32_t* Vs = stg + st * STG + KSZ;
#pragma unroll
        for (int i = 0; i < 4; i++) {
            int l = tid + i * 128;
            int d = l >> 3, c = (l & 7) * 4;
            CP_ASYNC16(smaddr(&Vs[d * 36 + c]),
                       vb + (size_t)d * TU + it * 32 + c);
        }
    };

    // ---------------- Pass 1: row sums ----------------
    float rs[2][2] = {{0.f, 0.f}, {0.f, 0.f}};
    prefK(0, 0); CP_COMMIT();
    for (int it = 0; it < 32; it++) {
        if (it + 1 < 32) { prefK(it + 1, (it + 1) & 1); CP_COMMIT(); CP_WAIT(1); }
        else { CP_WAIT(0); }
        __syncthreads();
        const uint32_t* Ks = stg + (it & 1) * STG;
#pragma unroll
        for (int ntp = 0; ntp < 4; ntp++) {
            uint32_t kr[4][4];
#pragma unroll
            for (int kt = 0; kt < 4; kt++)
                ldsm4(kr[kt], Ks + (ntp * 16 + lrowB) * 36 + kt * 8 + lcolB);
            uint32_t mua = mskU[it * 32 + ntp * 8 + t4];
            uint32_t mub = mskU[it * 32 + ntp * 8 + 4 + t4];
            float2 mka = __half22float2(*(__half2*)&mua);
            float2 mkb = __half22float2(*(__half2*)&mub);
#pragma unroll
            for (int m = 0; m < 2; m++) {
                float ca[4] = {0.f, 0.f, 0.f, 0.f};
                float cb[4] = {0.f, 0.f, 0.f, 0.f};
#pragma unroll
                for (int kt = 0; kt < 4; kt++) {
                    mma_f16(ca, qf[m][kt], &kr[kt][0]);
                    mma_f16(cb, qf[m][kt], &kr[kt][2]);
                }
                rs[m][0] += ex2f(fmaf(ca[0], L2E, mka.x))
                          + ex2f(fmaf(ca[1], L2E, mka.y))
                          + ex2f(fmaf(cb[0], L2E, mkb.x))
                          + ex2f(fmaf(cb[1], L2E, mkb.y));
                rs[m][1] += ex2f(fmaf(ca[2], L2E, mka.x))
                          + ex2f(fmaf(ca[3], L2E, mka.y))
                          + ex2f(fmaf(cb[2], L2E, mkb.x))
                          + ex2f(fmaf(cb[3], L2E, mkb.y));
            }
        }
        __syncthreads();
    }
#pragma unroll
    for (int m = 0; m < 2; m++)
#pragma unroll
        for (int hh = 0; hh < 2; hh++) {
            float s = rs[m][hh];
            s += __shfl_xor_sync(0xffffffffu, s, 1);
            s += __shfl_xor_sync(0xffffffffu, s, 2);
            if (t4 == 0) ILs[warp * 32 + m * 16 + g + hh * 8] = 1.0f / s;
        }
    __syncthreads();
    float il[2][2];
#pragma unroll
    for (int m = 0; m < 2; m++) {
        il[m][0] = ILs[warp * 32 + m * 16 + g];
        il[m][1] = ILs[warp * 32 + m * 16 + g + 8];
    }

    // ---------------- Pass 2: PV first, p-write after ----------------
    float accv[2][8][4];
#pragma unroll
    for (int m = 0; m < 2; m++)
#pragma unroll
        for (int dt = 0; dt < 8; dt++)
#pragma unroll
            for (int i = 0; i < 4; i++) accv[m][dt][i] = 0.f;

    prefK(0, 0); prefV(0, 0); CP_COMMIT();
    for (int it = 0; it < 32; it++) {
        if (it + 1 < 32) {
            prefK(it + 1, (it + 1) & 1); prefV(it + 1, (it + 1) & 1);
            CP_COMMIT(); CP_WAIT(1);
        } else { CP_WAIT(0); }
        __syncthreads();
        const uint32_t* Ks = stg + (it & 1) * STG;
        const uint32_t* Vs = Ks + KSZ;
#pragma unroll
        for (int ntp = 0; ntp < 4; ntp++) {
            uint32_t kr[4][4];
#pragma unroll
            for (int kt = 0; kt < 4; kt++)
                ldsm4(kr[kt], Ks + (ntp * 16 + lrowB) * 36 + kt * 8 + lcolB);
            uint32_t mua = mskU[it * 32 + ntp * 8 + t4];
            uint32_t mub = mskU[it * 32 + ntp * 8 + 4 + t4];
            float2 mka = __half22float2(*(__half2*)&mua);
            float2 mkb = __half22float2(*(__half2*)&mub);

            uint32_t pf[2][4];
#pragma unroll
            for (int m = 0; m < 2; m++) {
                float ca[4] = {0.f, 0.f, 0.f, 0.f};
                float cb[4] = {0.f, 0.f, 0.f, 0.f};
#pragma unroll
                for (int kt = 0; kt < 4; kt++) {
                    mma_f16(ca, qf[m][kt], &kr[kt][0]);
                    mma_f16(cb, qf[m][kt], &kr[kt][2]);
                }
                pf[m][0] = packh2(ex2f(fmaf(ca[0], L2E, mka.x)),
                                  ex2f(fmaf(ca[1], L2E, mka.y)));
                pf[m][1] = packh2(ex2f(fmaf(ca[2], L2E, mka.x)),
                                  ex2f(fmaf(ca[3], L2E, mka.y)));
                pf[m][2] = packh2(ex2f(fmaf(cb[0], L2E, mkb.x)),
                                  ex2f(fmaf(cb[1], L2E, mkb.y)));
                pf[m][3] = packh2(ex2f(fmaf(cb[2], L2E, mkb.x)),
                                  ex2f(fmaf(cb[3], L2E, mkb.y)));
            }

            // PV MMAs first (tensor pipe fed immediately)
            const int ku = ntp * 8;
#pragma unroll
            for (int dp = 0; dp < 4; dp++) {
                uint32_t vr[4];
                ldsm4(vr, Vs + (dp * 16 + lrowB) * 36 + ku + lcolB);
#pragma unroll
                for (int m = 0; m < 2; m++) {
                    mma_f16(accv[m][2 * dp], pf[m], &vr[0]);
                    mma_f16(accv[m][2 * dp + 1], pf[m], &vr[2]);
                }
            }

            // p-write after, from pf (p = fp16(e) * il)
            if (WRITEP) {
#pragma unroll
                for (int m = 0; m < 2; m++) {
                    int row = s0 + warp * 32 + m * 16 + g;
                    int col = it * 64 + ntp * 16 + t4 * 2;
                    float2 fa = unpackh2(pf[m][0]);
                    float2 fb = unpackh2(pf[m][1]);
                    float2 fc = unpackh2(pf[m][2]);
                    float2 fd = unpackh2(pf[m][3]);
                    float* o0 = attn_out + ((size_t)bh * SS + row) * SS + col;
                    float* o1 = attn_out + ((size_t)bh * SS + row + 8) * SS + col;
                    float2 p0a = {fa.x * il[m][0], fa.y * il[m][0]};
                    float2 p1a = {fb.x * il[m][1], fb.y * il[m][1]};
                    float2 p0b = {fc.x * il[m][0], fc.y * il[m][0]};
                    float2 p1b = {fd.x * il[m][1], fd.y * il[m][1]};
                    *(float2*)o0 = p0a;
                    *(float2*)(o0 + 8) = p0b;
                    *(float2*)o1 = p1a;
                    *(float2*)(o1 + 8) = p1b;
                }
            }
        }
        __syncthreads();
    }

    // ctx epilogue: scale by invL, store fp16
#pragma unroll
    for (int m = 0; m < 2; m++) {
        int mr = warp * 32 + m * 16 + g;
#pragma unroll
        for (int dt = 0; dt < 8; dt++) {
            uint32_t o0 = packh2(accv[m][dt][0] * il[m][0],
                                 accv[m][dt][1] * il[m][0]);
            uint32_t o1 = packh2(accv[m][dt][2] * il[m][1],
                                 accv[m][dt][3] * il[m][1]);
            ctx[((size_t)b * SS + s0 + mr) * KU + h * 32 + dt * 4 + t4] = o0;
            ctx[((size_t)b * SS + s0 + mr + 8) * KU + h * 32 + dt * 4 + t4] = o1;
        }
    }
}

// ---------------------------------------------------------------------------
extern "C" void kernel_launch(void* const* d_in, const int* in_sizes, int n_in,
                              void* d_out, int out_size)
{
    const float* q    = (const float*)d_in[0];
    const float* k    = (const float*)d_in[1];
    const float* v    = (const float*)d_in[2];
    const float* mask = (const float*)d_in[3];
    const float* wq   = (const float*)d_in[4];
    const float* bq   = (const float*)d_in[5];
    const float* wk   = (const float*)d_in[6];
    const float* bk   = (const float*)d_in[7];
    const float* wv   = (const float*)d_in[8];
    const float* bv   = (const float*)d_in[9];
    const float* wo   = (const float*)d_in[10];
    const float* bo   = (const float*)d_in[11];
    float* out = (float*)d_out;

    uint32_t *qh, *kh, *vh, *wqp, *wkp, *wvp, *wop, *qp, *kp, *vp, *vpt, *ctx;
    cudaGetSymbolAddress((void**)&qh,  g_qh);
    cudaGetSymbolAddress((void**)&kh,  g_kh);
    cudaGetSymbolAddress((void**)&vh,  g_vh);
    cudaGetSymbolAddress((void**)&wqp, g_wqp);
    cudaGetSymbolAddress((void**)&wkp, g_wkp);
    cudaGetSymbolAddress((void**)&wvp, g_wvp);
    cudaGetSymbolAddress((void**)&wop, g_wop);
    cudaGetSymbolAddress((void**)&qp,  g_qp);
    cudaGetSymbolAddress((void**)&kp,  g_kp);
    cudaGetSymbolAddress((void**)&vp,  g_vp);
    cudaGetSymbolAddress((void**)&vpt, g_vpt);
    cudaGetSymbolAddress((void**)&ctx, g_ctx);

    bool attn_in_out = ((size_t)out_size >= OUT_ELEMS + ATTN_ELEMS);
    float* attn_out = attn_in_out ? (out + OUT_ELEMS) : nullptr;

    const int DYN_G = 2 * (128 * 36 + 32 * 136) * 4;        // 71680
    const int DYN_A = (1024 + 128 + 2 * (64 * 36 * 2)) * 4; // 41472
    cudaFuncSetAttribute(proj_qkv_tc, cudaFuncAttributeMaxDynamicSharedMemorySize, DYN_G);
    cudaFuncSetAttribute(out_proj_tc, cudaFuncAttributeMaxDynamicSharedMemorySize, DYN_G);
    cudaFuncSetAttribute(attn_fused<true>,  cudaFuncAttributeMaxDynamicSharedMemorySize, DYN_A);
    cudaFuncSetAttribute(attn_fused<false>, cudaFuncAttributeMaxDynamicSharedMemorySize, DYN_A);

    conv_all<<<2048, 256>>>(
        (const float4*)q, (const float4*)k, (const float4*)v,
        wq, wk, wv, wo,
        qh, kh, vh, wqp, wkp, wvp, wop);

    proj_qkv_tc<<<dim3(DD / 128, MROWS / 128, 3), 256, DYN_G>>>(
        qh, kh, vh, wqp, wkp, wvp, bq, bk, bv, qp, kp, vp);

    transpose_v<<<dim3(SS / 64, BB * HH), 256>>>(vp, vpt);

    if (attn_in_out)
        attn_fused<true><<<dim3(SS / 128, BB * HH), 128, DYN_A>>>(
            qp, kp, vpt, mask, attn_out, ctx);
    else
        attn_fused<false><<<dim3(SS / 128, BB * HH), 128, DYN_A>>>(
            qp, kp, vpt, mask, attn_out, ctx);

    out_proj_tc<<<dim3(DD / 128, MROWS / 128), 256, DYN_G>>>(ctx, wop, bo, out);
}